// round 9
// baseline (speedup 1.0000x reference)
#include <cuda_runtime.h>
#include <cuda_fp16.h>
#include <cstdint>

#define NN 8192
#define FIN 256
#define FOUT 128
#define GAT_ALPHA 0.2f
#define NT (NN / 128)           // j-tiles = 64
#define LOG2E 1.4426950408889634f

// ---------------- scratch (allocation-free: __device__ globals) ----------------
__device__ __half    g_Whh[NN * FOUT];    // Wh fp16
__device__ float     g_s[NN];             // Wh @ a[0:128]   (raw)
__device__ float     g_t[NN];             // (Wh @ a[128:256]) * log2(e)
__device__ unsigned  g_tmax_u = 0;        // order-encoded float max of raw t

__device__ __forceinline__ unsigned fenc(float f) {
    int i = __float_as_int(f);
    return (i >= 0) ? ((unsigned)i + 0x80000000u) : (unsigned)(~i);
}
__device__ __forceinline__ float fdec(unsigned u) {
    return (u >= 0x80000000u) ? __int_as_float((int)(u - 0x80000000u))
                              : __int_as_float((int)~u);
}

// ---------------- Kernel 1: Wh = h @ W (fp32) -> fp16, s, t ------------------
__global__ __launch_bounds__(256) void wh_kernel(const float* __restrict__ h,
                                                 const float* __restrict__ W,
                                                 const float* __restrict__ a)
{
    __shared__ float hs[64 * 36];
    __shared__ float Ws[32 * 132];

    const int tid = threadIdx.x;
    const int i0  = blockIdx.x * 64;
    const int tx  = tid & 15;
    const int ty  = tid >> 4;

    float acc[4][8];
#pragma unroll
    for (int i = 0; i < 4; i++)
#pragma unroll
        for (int u = 0; u < 8; u++) acc[i][u] = 0.f;

    for (int kt = 0; kt < FIN; kt += 32) {
        __syncthreads();
#pragma unroll
        for (int q = 0; q < 2; q++) {
            int lin = tid + q * 256;
            int r = lin >> 3, c4 = (lin & 7) * 4;
            *(float4*)&hs[r * 36 + c4] =
                *(const float4*)&h[(size_t)(i0 + r) * FIN + kt + c4];
        }
#pragma unroll
        for (int q = 0; q < 4; q++) {
            int lin = tid + q * 256;
            int r = lin >> 5, c4 = (lin & 31) * 4;
            *(float4*)&Ws[r * 132 + c4] =
                *(const float4*)&W[(size_t)(kt + r) * FOUT + c4];
        }
        __syncthreads();
#pragma unroll 4
        for (int k = 0; k < 32; k++) {
            float bv[8];
#pragma unroll
            for (int u = 0; u < 8; u++) bv[u] = Ws[k * 132 + tx * 8 + u];
#pragma unroll
            for (int i = 0; i < 4; i++) {
                float av = hs[(ty * 4 + i) * 36 + k];
#pragma unroll
                for (int u = 0; u < 8; u++) acc[i][u] = fmaf(av, bv[u], acc[i][u]);
            }
        }
    }

    float a1[8], a2[8];
#pragma unroll
    for (int u = 0; u < 8; u++) {
        a1[u] = a[tx * 8 + u];
        a2[u] = a[FOUT + tx * 8 + u];
    }
#pragma unroll
    for (int i = 0; i < 4; i++) {
        int rg = i0 + ty * 4 + i;
        float ps = 0.f, pt = 0.f;
#pragma unroll
        for (int u = 0; u < 8; u++) {
            float v = acc[i][u];
            g_Whh[(size_t)rg * FOUT + tx * 8 + u] = __float2half(v);
            ps = fmaf(v, a1[u], ps);
            pt = fmaf(v, a2[u], pt);
        }
#pragma unroll
        for (int off = 1; off < 16; off <<= 1) {
            ps += __shfl_xor_sync(0xffffffffu, ps, off);
            pt += __shfl_xor_sync(0xffffffffu, pt, off);
        }
        if (tx == 0) {
            g_s[rg] = ps;
            g_t[rg] = pt * LOG2E;
            atomicMax(&g_tmax_u, fenc(pt));   // idempotent across replays
        }
    }
}

// ---------------- mma helpers ----------------
__device__ __forceinline__ void ldsm4(uint32_t& r0, uint32_t& r1, uint32_t& r2,
                                      uint32_t& r3, uint32_t addr)
{
    asm volatile("ldmatrix.sync.aligned.m8n8.x4.shared.b16 {%0,%1,%2,%3}, [%4];"
                 : "=r"(r0), "=r"(r1), "=r"(r2), "=r"(r3) : "r"(addr));
}
__device__ __forceinline__ void ldsm4t(uint32_t& r0, uint32_t& r1, uint32_t& r2,
                                       uint32_t& r3, uint32_t addr)
{
    asm volatile("ldmatrix.sync.aligned.m8n8.x4.trans.shared.b16 {%0,%1,%2,%3}, [%4];"
                 : "=r"(r0), "=r"(r1), "=r"(r2), "=r"(r3) : "r"(addr));
}
__device__ __forceinline__ void mma16816(float* c, uint32_t a0, uint32_t a1,
                                         uint32_t a2, uint32_t a3,
                                         uint32_t b0, uint32_t b1)
{
    asm volatile(
        "mma.sync.aligned.m16n8k16.row.col.f32.f16.f16.f32 "
        "{%0,%1,%2,%3}, {%4,%5,%6,%7}, {%8,%9}, {%0,%1,%2,%3};"
        : "+f"(c[0]), "+f"(c[1]), "+f"(c[2]), "+f"(c[3])
        : "r"(a0), "r"(a1), "r"(a2), "r"(a3), "r"(b0), "r"(b1));
}
__device__ __forceinline__ float ex2(float x) {
    float r;
    asm("ex2.approx.f32 %0, %1;" : "=f"(r) : "f"(x));
    return r;
}
__device__ __forceinline__ void cpa16(uint32_t dst, const void* src) {
    asm volatile("cp.async.cg.shared.global [%0], [%1], 16;" :: "r"(dst), "l"(src));
}

// ---------------- Kernel 2: warp-specialized fixed-max attention -------------
// 32 rows/CTA, 256 CTAs, 2/SM (all resident). Warps 0-3: softmax producers
// (adj LDG 1 tile ahead, t via L1 __ldg, write Ps). Warps 4-7: MMA consumers
// (whh cp.async double-buffer, m16n64 each). Named-barrier ring:
//   FULL0=1 FULL1=2 (producer arrive / consumer sync, 256)
//   FREE0=3 FREE1=4 (consumer arrive / producer sync, 256)
//   CONS =5 (consumer-only, 128) after cp.async.wait_group
#define SMEM_BYTES ((2 * 128 * 136 + 2 * 32 * 136) * 2 + 32 * 4)

__global__ __launch_bounds__(256, 2) void attn_kernel(const int* __restrict__ adj,
                                                      float* __restrict__ out)
{
    extern __shared__ __align__(16) char smem[];
    __half* whh  = (__half*)smem;                  // [2][128*136]
    __half* Ps   = whh + 2 * 128 * 136;            // [2][32*136]
    float*  linv = (float*)(Ps + 2 * 32 * 136);    // [32]

    const int tid = threadIdx.x;
    const int i0  = blockIdx.x * 32;

    float acc[8][4];   // consumer accumulators (live only in consumer path)

    if (tid < 128) {
        // ================= PRODUCERS (warps 0-3) =================
        const int er = tid >> 2;       // row 0..31
        const int pj = tid & 3;        // 32-col chunk

        const float s_r  = g_s[i0 + er];
        const float tmax = fdec(g_tmax_u);
        const float x    = s_r + tmax;
        const float mhat = fmaxf(x, GAT_ALPHA * x);
        const float A    = (s_r - mhat) * LOG2E;
        const float B    = (GAT_ALPHA * s_r - mhat) * LOG2E;

        const int4*   aptr = (const int4*)(adj + (size_t)(i0 + er) * NN) + pj * 8;
        const float4* tptr = (const float4*)g_t + pj * 8;

        int4 cur[8];
#pragma unroll
        for (int q = 0; q < 8; q++) cur[q] = aptr[q];    // tile 0

        float l_acc = 0.f;

        for (int jt = 0; jt < NT; jt++) {
            const int b = jt & 1;
            __half* Psb = Ps + b * 32 * 136;

            if (jt >= 2) {
                int bid = 3 + b;      // FREE[b]
                asm volatile("bar.sync %0, 256;" :: "r"(bid) : "memory");
            }

            // e-phase: p = exp2(max(A + t', fma(0.2, t', B))), adj-masked
#pragma unroll
            for (int q = 0; q < 8; q++) {
                float4 tq = __ldg(&tptr[jt * 32 + q]);
                int4 av = cur[q];
                float e0 = fmaxf(A + tq.x, fmaf(GAT_ALPHA, tq.x, B));
                float e1 = fmaxf(A + tq.y, fmaf(GAT_ALPHA, tq.y, B));
                float e2 = fmaxf(A + tq.z, fmaf(GAT_ALPHA, tq.z, B));
                float e3 = fmaxf(A + tq.w, fmaf(GAT_ALPHA, tq.w, B));
                e0 = (av.x > 0) ? e0 : -INFINITY;
                e1 = (av.y > 0) ? e1 : -INFINITY;
                e2 = (av.z > 0) ? e2 : -INFINITY;
                e3 = (av.w > 0) ? e3 : -INFINITY;
                float p0 = ex2(e0), p1 = ex2(e1), p2 = ex2(e2), p3 = ex2(e3);
                l_acc += (p0 + p1) + (p2 + p3);
                uint2 st;
                ((__half2*)&st)[0] = __floats2half2_rn(p0, p1);
                ((__half2*)&st)[1] = __floats2half2_rn(p2, p3);
                *(uint2*)&Psb[er * 136 + pj * 32 + q * 4] = st;
            }

            // prefetch adj for next tile (consumed one full tile later)
            if (jt + 1 < NT) {
#pragma unroll
                for (int q = 0; q < 8; q++) cur[q] = aptr[(jt + 1) * 32 + q];
            }

            __threadfence_block();    // publish Ps[b] before arrive
            {
                int bid = 1 + b;      // FULL[b]
                asm volatile("bar.arrive %0, 256;" :: "r"(bid) : "memory");
            }
        }

        // final l reduction (4 threads per row, adjacent lanes)
        l_acc += __shfl_xor_sync(0xffffffffu, l_acc, 1);
        l_acc += __shfl_xor_sync(0xffffffffu, l_acc, 2);
        if (pj == 0) linv[er] = 1.0f / l_acc;

    } else {
        // ================= CONSUMERS (warps 4-7) =================
        const int ctid = tid - 128;
        const int lane = ctid & 31;
        const int cwid = ctid >> 5;
        const int wm   = cwid >> 1;    // 0..1 : 16-row slab
        const int wn   = cwid & 1;     // 0..1 : 64-col slab

        // prefetch whh tile 0 into buffer 0
#pragma unroll
        for (int q = 0; q < 16; q++) {
            int lin = ctid + q * 128;
            int r = lin >> 4, c = (lin & 15) * 8;
            cpa16((uint32_t)__cvta_generic_to_shared(&whh[r * 136 + c]),
                  &g_Whh[(size_t)r * FOUT + c]);
        }
        asm volatile("cp.async.commit_group;");

#pragma unroll
        for (int nb = 0; nb < 8; nb++)
#pragma unroll
            for (int v = 0; v < 4; v++) acc[nb][v] = 0.f;

        const int kA_row = wm * 16 + (lane & 15);
        const int kB_row = (lane & 7) + 8 * ((lane >> 3) & 1);
        const int kB_col = wn * 64 + 8 * (lane >> 4);

        for (int jt = 0; jt < NT; jt++) {
            const int b = jt & 1;
            __half* whb = whh + b * 128 * 136;
            __half* Psb = Ps + b * 32 * 136;

            {
                int bid = 1 + b;      // FULL[b]: Ps[b] ready; consumers aligned
                asm volatile("bar.sync %0, 256;" :: "r"(bid) : "memory");
            }

            // prefetch whh for jt+1 (safe: all consumers past MMA[jt-1])
            if (jt + 1 < NT) {
                const int j1 = (jt + 1) * 128;
                __half* whn = whh + (b ^ 1) * 128 * 136;
#pragma unroll
                for (int q = 0; q < 16; q++) {
                    int lin = ctid + q * 128;
                    int r = lin >> 4, c = (lin & 15) * 8;
                    cpa16((uint32_t)__cvta_generic_to_shared(&whn[r * 136 + c]),
                          &g_Whh[(size_t)(j1 + r) * FOUT + c]);
                }
            }
            asm volatile("cp.async.commit_group;");
            asm volatile("cp.async.wait_group 1;");
            asm volatile("bar.sync 5, 128;" ::: "memory");  // whh[b] valid for all

            // MMA: acc += P @ Wh   (each warp m16 n64)
#pragma unroll
            for (int ks = 0; ks < 8; ks++) {
                uint32_t a0, a1, a2, a3;
                uint32_t aaddr = (uint32_t)__cvta_generic_to_shared(
                    &Psb[kA_row * 136 + ks * 16 + (lane >> 4) * 8]);
                ldsm4(a0, a1, a2, a3, aaddr);
#pragma unroll
                for (int ng = 0; ng < 4; ng++) {
                    const int nb0 = ng * 2;
                    const int boff = (ks * 16 + kB_row) * 136 + kB_col + ng * 16;
                    uint32_t b0, b1, b2, b3;
                    uint32_t baddr = (uint32_t)__cvta_generic_to_shared(&whb[boff]);
                    ldsm4t(b0, b1, b2, b3, baddr);
                    mma16816(acc[nb0],     a0, a1, a2, a3, b0, b1);
                    mma16816(acc[nb0 + 1], a0, a1, a2, a3, b2, b3);
                }
            }

            {
                int bid = 3 + b;      // FREE[b]: Ps[b] consumed
                asm volatile("bar.arrive %0, 256;" :: "r"(bid) : "memory");
            }
        }
    }

    __syncthreads();                 // linv published; all work done

    if (tid >= 128) {
        // ---- epilogue: normalize, ELU, store (consumers hold acc) ----
        const int ctid = tid - 128;
        const int lane = ctid & 31;
        const int cwid = ctid >> 5;
        const int wm   = cwid >> 1;
        const int wn   = cwid & 1;
        const float li_lo = linv[wm * 16 + (lane >> 2)];
        const float li_hi = linv[wm * 16 + 8 + (lane >> 2)];
        const int rg0 = i0 + wm * 16 + (lane >> 2);
#pragma unroll
        for (int nb = 0; nb < 8; nb++) {
            const int col = wn * 64 + nb * 8 + (lane & 3) * 2;
            float v0 = acc[nb][0] * li_lo, v1 = acc[nb][1] * li_lo;
            float v2 = acc[nb][2] * li_hi, v3 = acc[nb][3] * li_hi;
            v0 = (v0 > 0.f) ? v0 : expm1f(v0);
            v1 = (v1 > 0.f) ? v1 : expm1f(v1);
            v2 = (v2 > 0.f) ? v2 : expm1f(v2);
            v3 = (v3 > 0.f) ? v3 : expm1f(v3);
            out[(size_t)rg0 * FOUT + col]           = v0;
            out[(size_t)rg0 * FOUT + col + 1]       = v1;
            out[(size_t)(rg0 + 8) * FOUT + col]     = v2;
            out[(size_t)(rg0 + 8) * FOUT + col + 1] = v3;
        }
    }
}

// ---------------- launch ----------------
extern "C" void kernel_launch(void* const* d_in, const int* in_sizes, int n_in,
                              void* d_out, int out_size)
{
    const float* h = nullptr;
    const int*   adj = nullptr;
    const float* W = nullptr;
    const float* a = nullptr;
    for (int i = 0; i < n_in; i++) {
        long s = in_sizes[i];
        if (s == (long)NN * FIN)        h   = (const float*)d_in[i];
        else if (s == (long)NN * NN)    adj = (const int*)d_in[i];
        else if (s == (long)FIN * FOUT) W   = (const float*)d_in[i];
        else if (s == 2 * FOUT)         a   = (const float*)d_in[i];
    }
    float* out = (float*)d_out;

    cudaFuncSetAttribute(attn_kernel,
                         cudaFuncAttributeMaxDynamicSharedMemorySize, SMEM_BYTES);

    wh_kernel<<<NN / 64, 256>>>(h, W, a);
    attn_kernel<<<NN / 32, 256, SMEM_BYTES>>>(adj, out);
}